// round 6
// baseline (speedup 1.0000x reference)
#include <cuda_runtime.h>
#include <math.h>
#include <stdint.h>
#include <cooperative_groups.h>
#include <cooperative_groups/reduce.h>
namespace cg = cooperative_groups;

// Problem constants
#define Bq   2
#define Lq   2048
#define DMq  512      // d_model
#define DIq  1024     // d_inner
#define DSq  16       // d_state
#define DTR  32       // dt_rank
#define NR   (Bq*Lq)  // 4096 rows

// ---------------- scratch (device globals; no runtime allocation) ----------
__device__ float g_h  [NR*DMq];        // layernorm output
__device__ float g_xz [NR*2*DIq];      // in_proj output (x | z)
__device__ float g_xcf[NR*DIq];        // conv+silu fwd
__device__ float g_xcb[NR*DIq];        // conv+silu bwd (reversed domain)
__device__ float g_xdf[NR*64];         // x_dbl fwd (cols 32..63 = B/C interleaved)
__device__ float g_xdb[NR*64];         // x_dbl bwd
__device__ float g_dtf[NR*DIq];        // dt fwd
__device__ float g_dtb[NR*DIq];        // dt bwd
__device__ float g_yf [NR*DIq];        // scan out fwd
__device__ float g_yb [NR*DIq];        // scan out bwd (reversed domain)

// ---------------- LayerNorm (+ residual copy) ------------------------------
__global__ void ln_kernel(const float* __restrict__ x, const float* __restrict__ w,
                          const float* __restrict__ b, float* __restrict__ out,
                          float* __restrict__ res)
{
    int row = blockIdx.x;
    int t   = threadIdx.x;          // 256 threads, 512 elems
    const float* xr = x + row*DMq;
    float v0 = xr[t], v1 = xr[t+256];
    if (res) { res[row*DMq+t] = v0; res[row*DMq+t+256] = v1; }
    float s = v0+v1, q = v0*v0 + v1*v1;
    #pragma unroll
    for (int o = 16; o; o >>= 1) {
        s += __shfl_xor_sync(0xffffffffu, s, o);
        q += __shfl_xor_sync(0xffffffffu, q, o);
    }
    __shared__ float ss[8], sq[8];
    if ((t & 31) == 0) { ss[t>>5] = s; sq[t>>5] = q; }
    __syncthreads();
    s = 0.f; q = 0.f;
    #pragma unroll
    for (int i = 0; i < 8; i++) { s += ss[i]; q += sq[i]; }
    float mu  = s * (1.f/DMq);
    float var = q * (1.f/DMq) - mu*mu;
    float r   = rsqrtf(var + 1e-5f);
    out[row*DMq+t]     = (v0-mu)*r*w[t]     + b[t];
    out[row*DMq+t+256] = (v1-mu)*r*w[t+256] + b[t+256];
}

// ---------------- TF32 tensor-core GEMM, cp.async 2-stage pipeline ---------
// C[m,n] = sum_k A[m,k]*B[n,k].
// ACT: 0 = none, 1 = softplus(v + bias[n]), 2 = B/C column interleave (x_proj)
struct GP { const float* A; const float* B; float* C; const float* bias; };

__device__ __forceinline__ uint32_t f2tf32(float x) {
    uint32_t r;
    asm("cvt.rna.tf32.f32 %0, %1;" : "=r"(r) : "f"(x));
    return r;
}

__device__ __forceinline__ void mma_tf32(float c[4],
    uint32_t a0, uint32_t a1, uint32_t a2, uint32_t a3,
    uint32_t b0, uint32_t b1)
{
    asm volatile(
        "mma.sync.aligned.m16n8k8.row.col.f32.tf32.tf32.f32 "
        "{%0,%1,%2,%3}, {%4,%5,%6,%7}, {%8,%9}, {%0,%1,%2,%3};"
        : "+f"(c[0]), "+f"(c[1]), "+f"(c[2]), "+f"(c[3])
        : "r"(a0), "r"(a1), "r"(a2), "r"(a3), "r"(b0), "r"(b1));
}

__device__ __forceinline__ void cp16(void* s, const void* gp) {
    uint32_t sa = (uint32_t)__cvta_generic_to_shared(s);
    asm volatile("cp.async.cg.shared.global [%0], [%1], 16;" :: "r"(sa), "l"(gp));
}

// column permutation for x_proj: dt cols 0..31 identity; B_n -> 32+2n, C_n -> 33+2n
__device__ __forceinline__ int bcperm(int c) {
    return c < 32 ? c : (c < 48 ? 32 + 2*(c-32) : 33 + 2*(c-48));
}

template<int BM,int BN,int WM,int WN,int ACT>
__global__ void __launch_bounds__((BM/WM)*(BN/WN)*32, 1)
mma_gemm(GP g0, GP g1, int M, int N, int K, int lda, int ldb, int ldc)
{
    constexpr int WARPS_M = BM/WM, WARPS_N = BN/WN;
    constexpr int THREADS = WARPS_M*WARPS_N*32;
    constexpr int MT = WM/16, NT = WN/8;
    GP g = blockIdx.z ? g1 : g0;

    __shared__ __align__(16) float As[2][BM][36];
    __shared__ __align__(16) float Bs[2][BN][36];

    int m0   = blockIdx.y * BM;
    int n0   = blockIdx.x * BN;
    int tid  = threadIdx.x;
    int lane = tid & 31;
    int warp = tid >> 5;
    int wm   = (warp / WARPS_N) * WM;
    int wn   = (warp % WARPS_N) * WN;
    int gq   = lane >> 2;      // 0..7
    int q    = lane & 3;       // 0..3

    float acc[MT][NT][4];
    #pragma unroll
    for (int i = 0; i < MT; i++)
        #pragma unroll
        for (int j = 0; j < NT; j++)
            #pragma unroll
            for (int r = 0; r < 4; r++) acc[i][j][r] = 0.f;

    const int KT = K >> 5;

    auto issue = [&](int st, int k0) {
        #pragma unroll
        for (int i = tid; i < BM*8; i += THREADS) {
            int r = i >> 3, c = (i & 7) * 4;
            cp16(&As[st][r][c], g.A + (size_t)(m0+r)*lda + k0 + c);
        }
        #pragma unroll
        for (int i = tid; i < BN*8; i += THREADS) {
            int r = i >> 3, c = (i & 7) * 4;
            cp16(&Bs[st][r][c], g.B + (size_t)(n0+r)*ldb + k0 + c);
        }
        asm volatile("cp.async.commit_group;");
    };

    issue(0, 0);

    for (int kt = 0; kt < KT; kt++) {
        if (kt + 1 < KT) {
            issue((kt+1) & 1, (kt+1) << 5);
            asm volatile("cp.async.wait_group 1;");
        } else {
            asm volatile("cp.async.wait_group 0;");
        }
        __syncthreads();

        int st = kt & 1;
        #pragma unroll
        for (int ks = 0; ks < 4; ks++) {
            int kk = ks*8;
            uint32_t af[MT][4], bf[NT][2];
            #pragma unroll
            for (int mt = 0; mt < MT; mt++) {
                int mr = wm + mt*16 + gq;
                af[mt][0] = f2tf32(As[st][mr  ][kk+q]);
                af[mt][1] = f2tf32(As[st][mr+8][kk+q]);
                af[mt][2] = f2tf32(As[st][mr  ][kk+q+4]);
                af[mt][3] = f2tf32(As[st][mr+8][kk+q+4]);
            }
            #pragma unroll
            for (int nt = 0; nt < NT; nt++) {
                int nr = wn + nt*8 + gq;
                bf[nt][0] = f2tf32(Bs[st][nr][kk+q]);
                bf[nt][1] = f2tf32(Bs[st][nr][kk+q+4]);
            }
            #pragma unroll
            for (int mt = 0; mt < MT; mt++)
                #pragma unroll
                for (int nt = 0; nt < NT; nt++)
                    mma_tf32(acc[mt][nt], af[mt][0], af[mt][1], af[mt][2], af[mt][3],
                             bf[nt][0], bf[nt][1]);
        }
        __syncthreads();
    }

    #pragma unroll
    for (int mt = 0; mt < MT; mt++) {
        #pragma unroll
        for (int nt = 0; nt < NT; nt++) {
            int m = m0 + wm + mt*16 + gq;
            int n = n0 + wn + nt*8 + 2*q;
            float c0 = acc[mt][nt][0], c1 = acc[mt][nt][1];
            float c2 = acc[mt][nt][2], c3 = acc[mt][nt][3];
            if constexpr (ACT == 1) {
                float b0v = g.bias[n], b1v = g.bias[n+1];
                c0 += b0v; c1 += b1v; c2 += b0v; c3 += b1v;
                c0 = fmaxf(c0, 0.f) + log1pf(expf(-fabsf(c0)));
                c1 = fmaxf(c1, 0.f) + log1pf(expf(-fabsf(c1)));
                c2 = fmaxf(c2, 0.f) + log1pf(expf(-fabsf(c2)));
                c3 = fmaxf(c3, 0.f) + log1pf(expf(-fabsf(c3)));
            }
            if constexpr (ACT == 2) {
                g.C[(size_t)m*ldc + bcperm(n)]       = c0;
                g.C[(size_t)m*ldc + bcperm(n+1)]     = c1;
                g.C[(size_t)(m+8)*ldc + bcperm(n)]   = c2;
                g.C[(size_t)(m+8)*ldc + bcperm(n+1)] = c3;
            } else {
                *reinterpret_cast<float2*>(g.C + (size_t)m*ldc + n)     = make_float2(c0, c1);
                *reinterpret_cast<float2*>(g.C + (size_t)(m+8)*ldc + n) = make_float2(c2, c3);
            }
        }
    }
}

// ---- out_proj with fused combine: A := 0.5*(yf[m] + yb[rev(m)]) -----------
template<int BM,int BN,int WM,int WN>
__global__ void __launch_bounds__((BM/WM)*(BN/WN)*32, 1)
mma_gemm_comb(const float* __restrict__ Ay, const float* __restrict__ Ab,
              const float* __restrict__ Bw, float* __restrict__ C,
              int M, int N, int K, int lda, int ldb, int ldc)
{
    constexpr int WARPS_M = BM/WM, WARPS_N = BN/WN;
    constexpr int THREADS = WARPS_M*WARPS_N*32;
    constexpr int MT = WM/16, NT = WN/8;

    __shared__ __align__(16) float As [2][BM][36];
    __shared__ __align__(16) float As2[2][BM][36];
    __shared__ __align__(16) float Bs [2][BN][36];

    int m0   = blockIdx.y * BM;
    int n0   = blockIdx.x * BN;
    // reversed-tile base for yb: same batch, rows (Lq-1-l0-BM+1 .. Lq-1-l0)
    int l0   = m0 & (Lq-1);
    int mb0  = (m0 & ~(Lq-1)) + (Lq - 1 - l0 - (BM-1));
    int tid  = threadIdx.x;
    int lane = tid & 31;
    int warp = tid >> 5;
    int wm   = (warp / WARPS_N) * WM;
    int wn   = (warp % WARPS_N) * WN;
    int gq   = lane >> 2;
    int q    = lane & 3;

    float acc[MT][NT][4];
    #pragma unroll
    for (int i = 0; i < MT; i++)
        #pragma unroll
        for (int j = 0; j < NT; j++)
            #pragma unroll
            for (int r = 0; r < 4; r++) acc[i][j][r] = 0.f;

    const int KT = K >> 5;

    auto issue = [&](int st, int k0) {
        #pragma unroll
        for (int i = tid; i < BM*8; i += THREADS) {
            int r = i >> 3, c = (i & 7) * 4;
            cp16(&As [st][r][c], Ay + (size_t)(m0 +r)*lda + k0 + c);
            cp16(&As2[st][r][c], Ab + (size_t)(mb0+r)*lda + k0 + c);
        }
        #pragma unroll
        for (int i = tid; i < BN*8; i += THREADS) {
            int r = i >> 3, c = (i & 7) * 4;
            cp16(&Bs[st][r][c], Bw + (size_t)(n0+r)*ldb + k0 + c);
        }
        asm volatile("cp.async.commit_group;");
    };

    issue(0, 0);

    for (int kt = 0; kt < KT; kt++) {
        if (kt + 1 < KT) {
            issue((kt+1) & 1, (kt+1) << 5);
            asm volatile("cp.async.wait_group 1;");
        } else {
            asm volatile("cp.async.wait_group 0;");
        }
        __syncthreads();

        int st = kt & 1;
        #pragma unroll
        for (int ks = 0; ks < 4; ks++) {
            int kk = ks*8;
            uint32_t af[MT][4], bf[NT][2];
            #pragma unroll
            for (int mt = 0; mt < MT; mt++) {
                int mr = wm + mt*16 + gq;
                int rr = BM-1-mr;          // reversed row for yb
                af[mt][0] = f2tf32(As[st][mr  ][kk+q]   + As2[st][rr  ][kk+q]);
                af[mt][1] = f2tf32(As[st][mr+8][kk+q]   + As2[st][rr-8][kk+q]);
                af[mt][2] = f2tf32(As[st][mr  ][kk+q+4] + As2[st][rr  ][kk+q+4]);
                af[mt][3] = f2tf32(As[st][mr+8][kk+q+4] + As2[st][rr-8][kk+q+4]);
            }
            #pragma unroll
            for (int nt = 0; nt < NT; nt++) {
                int nr = wn + nt*8 + gq;
                bf[nt][0] = f2tf32(Bs[st][nr][kk+q]);
                bf[nt][1] = f2tf32(Bs[st][nr][kk+q+4]);
            }
            #pragma unroll
            for (int mt = 0; mt < MT; mt++)
                #pragma unroll
                for (int nt = 0; nt < NT; nt++)
                    mma_tf32(acc[mt][nt], af[mt][0], af[mt][1], af[mt][2], af[mt][3],
                             bf[nt][0], bf[nt][1]);
        }
        __syncthreads();
    }

    #pragma unroll
    for (int mt = 0; mt < MT; mt++) {
        #pragma unroll
        for (int nt = 0; nt < NT; nt++) {
            int m = m0 + wm + mt*16 + gq;
            int n = n0 + wn + nt*8 + 2*q;
            *reinterpret_cast<float2*>(C + (size_t)m*ldc + n) =
                make_float2(0.5f*acc[mt][nt][0], 0.5f*acc[mt][nt][1]);
            *reinterpret_cast<float2*>(C + (size_t)(m+8)*ldc + n) =
                make_float2(0.5f*acc[mt][nt][2], 0.5f*acc[mt][nt][3]);
        }
    }
}

// ---------------- causal depthwise conv (K=4) + SiLU, fwd & bwd ------------
__global__ void conv_kernel(const float* __restrict__ xz,
                            const float* __restrict__ wf, const float* __restrict__ bf,
                            const float* __restrict__ wb, const float* __restrict__ bb,
                            float* __restrict__ of, float* __restrict__ ob)
{
    int idx = blockIdx.x*256 + threadIdx.x;      // over NR*DIq
    bool rev = blockIdx.y;
    const float* w  = rev ? wb : wf;
    const float* bi = rev ? bb : bf;
    float*       o  = rev ? ob : of;

    int d   = idx & (DIq-1);
    int row = idx >> 10;
    int l   = row & (Lq-1);
    int b   = row >> 11;

    float acc = bi[d];
    #pragma unroll
    for (int k = 0; k < 4; k++) {
        int ls = l - 3 + k;
        if (ls >= 0) {
            int lsrc = rev ? (Lq-1-ls) : ls;
            acc = fmaf(w[d*4+k], xz[(size_t)(b*Lq + lsrc)*(2*DIq) + d], acc);
        }
    }
    o[idx] = acc / (1.f + __expf(-acc));   // silu
}

// ---------------- selective scan (both branches in one launch) -------------
// 16 lanes per channel (one per state); warp = 2 channels; block = 8 channels.
// PF-step groups: h chain first, then 4 hardware reductions (redux via cg),
// branch-free select epilogue.
#define PF 4
__global__ void scan_kernel(
    const float* __restrict__ xcf, const float* __restrict__ dtf, const float* __restrict__ xdf,
    const float* __restrict__ Alf, const float* __restrict__ Df,
    const float* __restrict__ xcb, const float* __restrict__ dtb, const float* __restrict__ xdb,
    const float* __restrict__ Alb, const float* __restrict__ Db,
    const float* __restrict__ xz,
    float* __restrict__ yfo, float* __restrict__ ybo)
{
    bool rev = blockIdx.z;
    const float* xc = rev ? xcb : xcf;
    const float* dt = rev ? dtb : dtf;
    const float* xd = rev ? xdb : xdf;
    const float* Al = rev ? Alb : Alf;
    const float* Dp = rev ? Db  : Df;
    float*       y  = rev ? ybo : yfo;

    int b = blockIdx.y;
    int d = blockIdx.x*8 + (threadIdx.x >> 4);
    int n = threadIdx.x & 15;

    auto tile16 = cg::tiled_partition<16>(cg::this_thread_block());

    float Areg = -expf(Al[d*DSq + n]);
    float Dd   = Dp[d];

    size_t base = (size_t)b * Lq;
    const float* fdt = dt + base*DIq + d;
    const float* fx  = xc + base*DIq + d;
    const float* fBC = xd + base*64 + 32 + 2*n;   // interleaved {B_n, C_n}
    float*       pyr = y  + base*DIq + d;
    const float* pz  = xz + (rev ? (base + Lq - 1) : base)*(size_t)(2*DIq) + DIq + d;
    int zstep = rev ? -(2*DIq) : (2*DIq);

    // preload group 0
    float bdt[PF], bx[PF], bB[PF], bC[PF];
    #pragma unroll
    for (int i = 0; i < PF; i++) {
        bdt[i] = fdt[i*DIq];
        bx[i]  = fx [i*DIq];
        float2 v = *reinterpret_cast<const float2*>(fBC + i*64);
        bB[i] = v.x; bC[i] = v.y;
    }
    fdt += PF*DIq; fx += PF*DIq; fBC += PF*64;

    float zv = 0.f;
    if (n < PF) zv = pz[n*zstep];          // lane n holds z for step n
    const float* fz = pz + PF*zstep;

    float h = 0.f;
    const int NG = Lq/PF;
    for (int grp = 0; grp < NG; grp++) {
        bool notlast = (grp + 1 < NG);
        float dtc[PF], xcu[PF], Bc[PF], Cc[PF];
        #pragma unroll
        for (int j = 0; j < PF; j++) { dtc[j]=bdt[j]; xcu[j]=bx[j]; Bc[j]=bB[j]; Cc[j]=bC[j]; }
        if (notlast) {
            #pragma unroll
            for (int j = 0; j < PF; j++) {
                bdt[j] = fdt[j*DIq];
                bx[j]  = fx [j*DIq];
                float2 v = *reinterpret_cast<const float2*>(fBC + j*64);
                bB[j] = v.x; bC[j] = v.y;
            }
            fdt += PF*DIq; fx += PF*DIq; fBC += PF*64;
        }
        // pipelined exps + short h chain
        float dA[PF], pv[PF];
        #pragma unroll
        for (int j = 0; j < PF; j++) dA[j] = __expf(dtc[j]*Areg);
        #pragma unroll
        for (int j = 0; j < PF; j++) {
            h = fmaf(dA[j], h, dtc[j]*Bc[j]*xcu[j]);
            pv[j] = h * Cc[j];
        }
        // 4 independent 16-lane reductions (hw redux on sm_103a)
        #pragma unroll
        for (int j = 0; j < PF; j++)
            pv[j] = cg::reduce(tile16, pv[j], cg::plus<float>());
        // branch-free epilogue: lane j owns step j
        float zcur = zv;
        if (notlast && n < PF) zv = fz[n*zstep];
        float psel = (n==0) ? pv[0]  : (n==1) ? pv[1]  : (n==2) ? pv[2]  : pv[3];
        float xsel = (n==0) ? xcu[0] : (n==1) ? xcu[1] : (n==2) ? xcu[2] : xcu[3];
        float sz   = zcur / (1.f + __expf(-zcur));
        float rv   = fmaf(xsel, Dd, psel) * sz;
        if (n < PF) pyr[n*DIq] = rv;
        if (notlast) fz += PF*zstep;
        pyr += PF*DIq;
    }
}

// ---------------- launcher -------------------------------------------------
extern "C" void kernel_launch(void* const* d_in, const int* in_sizes, int n_in,
                              void* d_out, int out_size)
{
    const float* hidden = (const float*)d_in[0];
    const float* norm_w = (const float*)d_in[1];
    const float* norm_b = (const float*)d_in[2];
    const float* W_in   = (const float*)d_in[3];
    const float* W_out  = (const float*)d_in[4];
    const float* cw_f = (const float*)d_in[5];
    const float* cb_f = (const float*)d_in[6];
    const float* xp_f = (const float*)d_in[7];
    const float* dw_f = (const float*)d_in[8];
    const float* db_f = (const float*)d_in[9];
    const float* Al_f = (const float*)d_in[10];
    const float* D_f  = (const float*)d_in[11];
    const float* cw_b = (const float*)d_in[12];
    const float* cb_b = (const float*)d_in[13];
    const float* xp_b = (const float*)d_in[14];
    const float* dw_b = (const float*)d_in[15];
    const float* db_b = (const float*)d_in[16];
    const float* Al_b = (const float*)d_in[17];
    const float* D_b  = (const float*)d_in[18];

    float* out = (float*)d_out;
    float* res = (out_size >= 2*NR*DMq) ? out + (size_t)NR*DMq : nullptr;

    float *h,*xz,*xcf,*xcb,*xdf,*xdb,*dtf,*dtb,*yf,*yb;
    cudaGetSymbolAddress((void**)&h,   g_h);
    cudaGetSymbolAddress((void**)&xz,  g_xz);
    cudaGetSymbolAddress((void**)&xcf, g_xcf);
    cudaGetSymbolAddress((void**)&xcb, g_xcb);
    cudaGetSymbolAddress((void**)&xdf, g_xdf);
    cudaGetSymbolAddress((void**)&xdb, g_xdb);
    cudaGetSymbolAddress((void**)&dtf, g_dtf);
    cudaGetSymbolAddress((void**)&dtb, g_dtb);
    cudaGetSymbolAddress((void**)&yf,  g_yf);
    cudaGetSymbolAddress((void**)&yb,  g_yb);

    // 1. LayerNorm (+ residual copy into second half of d_out)
    ln_kernel<<<NR, 256>>>(hidden, norm_w, norm_b, h, res);

    // 2. in_proj: (4096,512) x (2048,512)^T -> (4096,2048)
    {
        GP g{h, W_in, xz, nullptr};
        mma_gemm<128,128,64,64,0><<<dim3(2*DIq/128, NR/128, 1), 128>>>(
            g, g, NR, 2*DIq, DMq, DMq, DMq, 2*DIq);
    }

    // 3. conv + silu, both branches
    conv_kernel<<<dim3(NR*DIq/256, 2), 256>>>(xz, cw_f, cb_f, cw_b, cb_b, xcf, xcb);

    // 4. x_proj: (4096,1024) x (64,1024)^T -> (4096,64), B/C interleaved out
    {
        GP gf{xcf, xp_f, xdf, nullptr}, gb{xcb, xp_b, xdb, nullptr};
        mma_gemm<64,64,32,32,2><<<dim3(1, NR/64, 2), 128>>>(
            gf, gb, NR, 64, DIq, DIq, DIq, 64);
    }

    // 5. dt_proj + bias + softplus: (4096,32) x (1024,32)^T -> (4096,1024)
    {
        GP gf{xdf, dw_f, dtf, db_f}, gb{xdb, dw_b, dtb, db_b};
        mma_gemm<128,64,64,32,1><<<dim3(DIq/64, NR/128, 2), 128>>>(
            gf, gb, NR, DIq, DTR, 64, DTR, DIq);
    }

    // 6. selective scan, both branches in one launch
    scan_kernel<<<dim3(DIq/8, Bq, 2), 128>>>(
        xcf, dtf, xdf, Al_f, D_f,
        xcb, dtb, xdb, Al_b, D_b,
        xz, yf, yb);

    // 7. out_proj with fused combine: 0.5*(yf + rev(yb)) @ W_out^T -> d_out
    mma_gemm_comb<128,64,64,32><<<dim3(DMq/64, NR/128, 1), 128>>>(
        yf, yb, W_out, out, NR, DMq, DIq, DIq, DIq, DMq);
}

// round 8
// speedup vs baseline: 1.4890x; 1.4890x over previous
#include <cuda_runtime.h>
#include <math.h>
#include <stdint.h>

// Problem constants
#define Bq   2
#define Lq   2048
#define DMq  512      // d_model
#define DIq  1024     // d_inner
#define DSq  16       // d_state
#define DTR  32       // dt_rank
#define NR   (Bq*Lq)  // 4096 rows

// ---------------- scratch (device globals; no runtime allocation) ----------
__device__ float g_h  [NR*DMq];        // layernorm output
__device__ float g_xz [NR*2*DIq];      // in_proj output (x | z)
__device__ float g_xcf[NR*DIq];        // conv+silu fwd
__device__ float g_xcb[NR*DIq];        // conv+silu bwd (reversed domain)
__device__ float g_xdf[NR*64];         // x_dbl fwd (cols 32..63 = B/C interleaved)
__device__ float g_xdb[NR*64];         // x_dbl bwd
__device__ float g_dtf[NR*DIq];        // dt fwd
__device__ float g_dtb[NR*DIq];        // dt bwd
__device__ float g_yf [NR*DIq];        // scan out fwd
__device__ float g_yb [NR*DIq];        // scan out bwd (reversed domain)
__device__ float g_yc [NR*DIq];        // combined

// ---------------- LayerNorm (+ residual copy) ------------------------------
__global__ void ln_kernel(const float* __restrict__ x, const float* __restrict__ w,
                          const float* __restrict__ b, float* __restrict__ out,
                          float* __restrict__ res)
{
    int row = blockIdx.x;
    int t   = threadIdx.x;          // 256 threads, 512 elems
    const float* xr = x + row*DMq;
    float v0 = xr[t], v1 = xr[t+256];
    if (res) { res[row*DMq+t] = v0; res[row*DMq+t+256] = v1; }
    float s = v0+v1, q = v0*v0 + v1*v1;
    #pragma unroll
    for (int o = 16; o; o >>= 1) {
        s += __shfl_xor_sync(0xffffffffu, s, o);
        q += __shfl_xor_sync(0xffffffffu, q, o);
    }
    __shared__ float ss[8], sq[8];
    if ((t & 31) == 0) { ss[t>>5] = s; sq[t>>5] = q; }
    __syncthreads();
    s = 0.f; q = 0.f;
    #pragma unroll
    for (int i = 0; i < 8; i++) { s += ss[i]; q += sq[i]; }
    float mu  = s * (1.f/DMq);
    float var = q * (1.f/DMq) - mu*mu;
    float r   = rsqrtf(var + 1e-5f);
    out[row*DMq+t]     = (v0-mu)*r*w[t]     + b[t];
    out[row*DMq+t+256] = (v1-mu)*r*w[t+256] + b[t+256];
}

// ---------------- TF32 tensor-core GEMM, cp.async 2-stage pipeline ---------
// C[m,n] = sum_k A[m,k]*B[n,k].
// ACT: 0 = none, 1 = softplus(v + bias[n]), 2 = B/C column interleave (x_proj)
struct GP { const float* A; const float* B; float* C; const float* bias; };

__device__ __forceinline__ uint32_t f2tf32(float x) {
    uint32_t r;
    asm("cvt.rna.tf32.f32 %0, %1;" : "=r"(r) : "f"(x));
    return r;
}

__device__ __forceinline__ void mma_tf32(float c[4],
    uint32_t a0, uint32_t a1, uint32_t a2, uint32_t a3,
    uint32_t b0, uint32_t b1)
{
    asm volatile(
        "mma.sync.aligned.m16n8k8.row.col.f32.tf32.tf32.f32 "
        "{%0,%1,%2,%3}, {%4,%5,%6,%7}, {%8,%9}, {%0,%1,%2,%3};"
        : "+f"(c[0]), "+f"(c[1]), "+f"(c[2]), "+f"(c[3])
        : "r"(a0), "r"(a1), "r"(a2), "r"(a3), "r"(b0), "r"(b1));
}

__device__ __forceinline__ void cp16(void* s, const void* gp) {
    uint32_t sa = (uint32_t)__cvta_generic_to_shared(s);
    asm volatile("cp.async.cg.shared.global [%0], [%1], 16;" :: "r"(sa), "l"(gp));
}

// column permutation for x_proj: dt cols 0..31 identity; B_n -> 32+2n, C_n -> 33+2n
__device__ __forceinline__ int bcperm(int c) {
    return c < 32 ? c : (c < 48 ? 32 + 2*(c-32) : 33 + 2*(c-48));
}

template<int BM,int BN,int WM,int WN,int ACT>
__global__ void __launch_bounds__((BM/WM)*(BN/WN)*32, 1)
mma_gemm(GP g0, GP g1, int M, int N, int K, int lda, int ldb, int ldc)
{
    constexpr int WARPS_M = BM/WM, WARPS_N = BN/WN;
    constexpr int THREADS = WARPS_M*WARPS_N*32;
    constexpr int MT = WM/16, NT = WN/8;
    GP g = blockIdx.z ? g1 : g0;

    __shared__ __align__(16) float As[2][BM][36];
    __shared__ __align__(16) float Bs[2][BN][36];

    int m0   = blockIdx.y * BM;
    int n0   = blockIdx.x * BN;
    int tid  = threadIdx.x;
    int lane = tid & 31;
    int warp = tid >> 5;
    int wm   = (warp / WARPS_N) * WM;
    int wn   = (warp % WARPS_N) * WN;
    int gq   = lane >> 2;      // 0..7
    int q    = lane & 3;       // 0..3

    float acc[MT][NT][4];
    #pragma unroll
    for (int i = 0; i < MT; i++)
        #pragma unroll
        for (int j = 0; j < NT; j++)
            #pragma unroll
            for (int r = 0; r < 4; r++) acc[i][j][r] = 0.f;

    const int KT = K >> 5;

    auto issue = [&](int st, int k0) {
        #pragma unroll
        for (int i = tid; i < BM*8; i += THREADS) {
            int r = i >> 3, c = (i & 7) * 4;
            cp16(&As[st][r][c], g.A + (size_t)(m0+r)*lda + k0 + c);
        }
        #pragma unroll
        for (int i = tid; i < BN*8; i += THREADS) {
            int r = i >> 3, c = (i & 7) * 4;
            cp16(&Bs[st][r][c], g.B + (size_t)(n0+r)*ldb + k0 + c);
        }
        asm volatile("cp.async.commit_group;");
    };

    issue(0, 0);

    for (int kt = 0; kt < KT; kt++) {
        if (kt + 1 < KT) {
            issue((kt+1) & 1, (kt+1) << 5);
            asm volatile("cp.async.wait_group 1;");
        } else {
            asm volatile("cp.async.wait_group 0;");
        }
        __syncthreads();

        int st = kt & 1;
        #pragma unroll
        for (int ks = 0; ks < 4; ks++) {
            int kk = ks*8;
            uint32_t af[MT][4], bf[NT][2];
            #pragma unroll
            for (int mt = 0; mt < MT; mt++) {
                int mr = wm + mt*16 + gq;
                af[mt][0] = f2tf32(As[st][mr  ][kk+q]);
                af[mt][1] = f2tf32(As[st][mr+8][kk+q]);
                af[mt][2] = f2tf32(As[st][mr  ][kk+q+4]);
                af[mt][3] = f2tf32(As[st][mr+8][kk+q+4]);
            }
            #pragma unroll
            for (int nt = 0; nt < NT; nt++) {
                int nr = wn + nt*8 + gq;
                bf[nt][0] = f2tf32(Bs[st][nr][kk+q]);
                bf[nt][1] = f2tf32(Bs[st][nr][kk+q+4]);
            }
            #pragma unroll
            for (int mt = 0; mt < MT; mt++)
                #pragma unroll
                for (int nt = 0; nt < NT; nt++)
                    mma_tf32(acc[mt][nt], af[mt][0], af[mt][1], af[mt][2], af[mt][3],
                             bf[nt][0], bf[nt][1]);
        }
        __syncthreads();
    }

    #pragma unroll
    for (int mt = 0; mt < MT; mt++) {
        #pragma unroll
        for (int nt = 0; nt < NT; nt++) {
            int m = m0 + wm + mt*16 + gq;
            int n = n0 + wn + nt*8 + 2*q;
            float c0 = acc[mt][nt][0], c1 = acc[mt][nt][1];
            float c2 = acc[mt][nt][2], c3 = acc[mt][nt][3];
            if constexpr (ACT == 1) {
                float b0v = g.bias[n], b1v = g.bias[n+1];
                c0 += b0v; c1 += b1v; c2 += b0v; c3 += b1v;
                c0 = fmaxf(c0, 0.f) + log1pf(expf(-fabsf(c0)));
                c1 = fmaxf(c1, 0.f) + log1pf(expf(-fabsf(c1)));
                c2 = fmaxf(c2, 0.f) + log1pf(expf(-fabsf(c2)));
                c3 = fmaxf(c3, 0.f) + log1pf(expf(-fabsf(c3)));
            }
            if constexpr (ACT == 2) {
                g.C[(size_t)m*ldc + bcperm(n)]       = c0;
                g.C[(size_t)m*ldc + bcperm(n+1)]     = c1;
                g.C[(size_t)(m+8)*ldc + bcperm(n)]   = c2;
                g.C[(size_t)(m+8)*ldc + bcperm(n+1)] = c3;
            } else {
                *reinterpret_cast<float2*>(g.C + (size_t)m*ldc + n)     = make_float2(c0, c1);
                *reinterpret_cast<float2*>(g.C + (size_t)(m+8)*ldc + n) = make_float2(c2, c3);
            }
        }
    }
}

// ---------------- causal depthwise conv (K=4) + SiLU, fwd & bwd ------------
__global__ void conv_kernel(const float* __restrict__ xz,
                            const float* __restrict__ wf, const float* __restrict__ bf,
                            const float* __restrict__ wb, const float* __restrict__ bb,
                            float* __restrict__ of, float* __restrict__ ob)
{
    int idx = blockIdx.x*256 + threadIdx.x;      // over NR*DIq
    bool rev = blockIdx.y;
    const float* w  = rev ? wb : wf;
    const float* bi = rev ? bb : bf;
    float*       o  = rev ? ob : of;

    int d   = idx & (DIq-1);
    int row = idx >> 10;
    int l   = row & (Lq-1);
    int b   = row >> 11;

    float acc = bi[d];
    #pragma unroll
    for (int k = 0; k < 4; k++) {
        int ls = l - 3 + k;
        if (ls >= 0) {
            int lsrc = rev ? (Lq-1-ls) : ls;
            acc = fmaf(w[d*4+k], xz[(size_t)(b*Lq + lsrc)*(2*DIq) + d], acc);
        }
    }
    o[idx] = acc / (1.f + __expf(-acc));   // silu
}

// ---------------- selective scan (both branches in one launch) -------------
// 16 lanes per channel (one per state); warp = 2 channels; block = 8 channels.
// PF-step groups: h chain first, then PF independent interleaved shuffle
// reductions, branch-free select epilogue (lane j owns step j).
#define PF 8
__global__ void scan_kernel(
    const float* __restrict__ xcf, const float* __restrict__ dtf, const float* __restrict__ xdf,
    const float* __restrict__ Alf, const float* __restrict__ Df,
    const float* __restrict__ xcb, const float* __restrict__ dtb, const float* __restrict__ xdb,
    const float* __restrict__ Alb, const float* __restrict__ Db,
    const float* __restrict__ xz,
    float* __restrict__ yfo, float* __restrict__ ybo)
{
    bool rev = blockIdx.z;
    const float* xc = rev ? xcb : xcf;
    const float* dt = rev ? dtb : dtf;
    const float* xd = rev ? xdb : xdf;
    const float* Al = rev ? Alb : Alf;
    const float* Dp = rev ? Db  : Df;
    float*       y  = rev ? ybo : yfo;

    int b = blockIdx.y;
    int d = blockIdx.x*8 + (threadIdx.x >> 4);
    int n = threadIdx.x & 15;

    float Areg = -expf(Al[d*DSq + n]);
    float Dd   = Dp[d];

    size_t base = (size_t)b * Lq;
    const float* fdt = dt + base*DIq + d;
    const float* fx  = xc + base*DIq + d;
    const float* fBC = xd + base*64 + 32 + 2*n;   // interleaved {B_n, C_n}
    float*       pyr = y  + base*DIq + d;
    const float* pz  = xz + (rev ? (base + Lq - 1) : base)*(size_t)(2*DIq) + DIq + d;
    int zstep = rev ? -(2*DIq) : (2*DIq);

    // preload group 0
    float bdt[PF], bx[PF], bB[PF], bC[PF];
    #pragma unroll
    for (int i = 0; i < PF; i++) {
        bdt[i] = fdt[i*DIq];
        bx[i]  = fx [i*DIq];
        float2 v = *reinterpret_cast<const float2*>(fBC + i*64);
        bB[i] = v.x; bC[i] = v.y;
    }
    fdt += PF*DIq; fx += PF*DIq; fBC += PF*64;

    float zv = 0.f;
    if (n < PF) zv = pz[n*zstep];          // lane n holds z for step n
    const float* fz = pz + PF*zstep;

    float h = 0.f;
    const int NG = Lq/PF;
    for (int grp = 0; grp < NG; grp++) {
        bool notlast = (grp + 1 < NG);
        float dtc[PF], xcu[PF], Bc[PF], Cc[PF];
        #pragma unroll
        for (int j = 0; j < PF; j++) { dtc[j]=bdt[j]; xcu[j]=bx[j]; Bc[j]=bB[j]; Cc[j]=bC[j]; }
        if (notlast) {
            #pragma unroll
            for (int j = 0; j < PF; j++) {
                bdt[j] = fdt[j*DIq];
                bx[j]  = fx [j*DIq];
                float2 v = *reinterpret_cast<const float2*>(fBC + j*64);
                bB[j] = v.x; bC[j] = v.y;
            }
            fdt += PF*DIq; fx += PF*DIq; fBC += PF*64;
        }
        // pipelined exps + short h chain
        float dA[PF], pv[PF];
        #pragma unroll
        for (int j = 0; j < PF; j++) dA[j] = __expf(dtc[j]*Areg);
        #pragma unroll
        for (int j = 0; j < PF; j++) {
            h = fmaf(dA[j], h, dtc[j]*Bc[j]*xcu[j]);
            pv[j] = h * Cc[j];
        }
        // PF independent 16-lane reductions; chains interleave per level
        #pragma unroll
        for (int off = 8; off; off >>= 1)
            #pragma unroll
            for (int j = 0; j < PF; j++)
                pv[j] += __shfl_xor_sync(0xffffffffu, pv[j], off, 16);
        // branch-free epilogue: lane j (0..PF-1) owns step j
        float zcur = zv;
        if (notlast && n < PF) zv = fz[n*zstep];
        float psel = pv[0], xsel = xcu[0];
        #pragma unroll
        for (int j = 1; j < PF; j++) {
            psel = (n == j) ? pv[j]  : psel;
            xsel = (n == j) ? xcu[j] : xsel;
        }
        float sz = zcur / (1.f + __expf(-zcur));
        float rv = fmaf(xsel, Dd, psel) * sz;
        if (n < PF) pyr[n*DIq] = rv;
        if (notlast) fz += PF*zstep;
        pyr += PF*DIq;
    }
}

// ---------------- combine fwd + reversed bwd -------------------------------
__global__ void combine_kernel(const float* __restrict__ yf, const float* __restrict__ yb,
                               float* __restrict__ yc)
{
    int idx = blockIdx.x*256 + threadIdx.x;
    int d   = idx & (DIq-1);
    int row = idx >> 10;
    int l   = row & (Lq-1);
    int b   = row >> 11;
    yc[idx] = 0.5f * (yf[idx] + yb[(size_t)(b*Lq + (Lq-1-l))*DIq + d]);
}

// ---------------- launcher -------------------------------------------------
extern "C" void kernel_launch(void* const* d_in, const int* in_sizes, int n_in,
                              void* d_out, int out_size)
{
    const float* hidden = (const float*)d_in[0];
    const float* norm_w = (const float*)d_in[1];
    const float* norm_b = (const float*)d_in[2];
    const float* W_in   = (const float*)d_in[3];
    const float* W_out  = (const float*)d_in[4];
    const float* cw_f = (const float*)d_in[5];
    const float* cb_f = (const float*)d_in[6];
    const float* xp_f = (const float*)d_in[7];
    const float* dw_f = (const float*)d_in[8];
    const float* db_f = (const float*)d_in[9];
    const float* Al_f = (const float*)d_in[10];
    const float* D_f  = (const float*)d_in[11];
    const float* cw_b = (const float*)d_in[12];
    const float* cb_b = (const float*)d_in[13];
    const float* xp_b = (const float*)d_in[14];
    const float* dw_b = (const float*)d_in[15];
    const float* db_b = (const float*)d_in[16];
    const float* Al_b = (const float*)d_in[17];
    const float* D_b  = (const float*)d_in[18];

    float* out = (float*)d_out;
    float* res = (out_size >= 2*NR*DMq) ? out + (size_t)NR*DMq : nullptr;

    float *h,*xz,*xcf,*xcb,*xdf,*xdb,*dtf,*dtb,*yf,*yb,*yc;
    cudaGetSymbolAddress((void**)&h,   g_h);
    cudaGetSymbolAddress((void**)&xz,  g_xz);
    cudaGetSymbolAddress((void**)&xcf, g_xcf);
    cudaGetSymbolAddress((void**)&xcb, g_xcb);
    cudaGetSymbolAddress((void**)&xdf, g_xdf);
    cudaGetSymbolAddress((void**)&xdb, g_xdb);
    cudaGetSymbolAddress((void**)&dtf, g_dtf);
    cudaGetSymbolAddress((void**)&dtb, g_dtb);
    cudaGetSymbolAddress((void**)&yf,  g_yf);
    cudaGetSymbolAddress((void**)&yb,  g_yb);
    cudaGetSymbolAddress((void**)&yc,  g_yc);

    // 1. LayerNorm (+ residual copy into second half of d_out)
    ln_kernel<<<NR, 256>>>(hidden, norm_w, norm_b, h, res);

    // 2. in_proj: (4096,512) x (2048,512)^T -> (4096,2048)
    {
        GP g{h, W_in, xz, nullptr};
        mma_gemm<128,128,64,64,0><<<dim3(2*DIq/128, NR/128, 1), 128>>>(
            g, g, NR, 2*DIq, DMq, DMq, DMq, 2*DIq);
    }

    // 3. conv + silu, both branches
    conv_kernel<<<dim3(NR*DIq/256, 2), 256>>>(xz, cw_f, cb_f, cw_b, cb_b, xcf, xcb);

    // 4. x_proj: (4096,1024) x (64,1024)^T -> (4096,64), B/C interleaved out
    {
        GP gf{xcf, xp_f, xdf, nullptr}, gb{xcb, xp_b, xdb, nullptr};
        mma_gemm<64,64,32,32,2><<<dim3(1, NR/64, 2), 128>>>(
            gf, gb, NR, 64, DIq, DIq, DIq, 64);
    }

    // 5. dt_proj + bias + softplus: (4096,32) x (1024,32)^T -> (4096,1024)
    {
        GP gf{xdf, dw_f, dtf, db_f}, gb{xdb, dw_b, dtb, db_b};
        mma_gemm<128,64,64,32,1><<<dim3(DIq/64, NR/128, 2), 128>>>(
            gf, gb, NR, DIq, DTR, 64, DTR, DIq);
    }

    // 6. selective scan, both branches in one launch
    scan_kernel<<<dim3(DIq/8, Bq, 2), 128>>>(
        xcf, dtf, xdf, Al_f, D_f,
        xcb, dtb, xdb, Al_b, D_b,
        xz, yf, yb);

    // 7. combine (un-reverse backward branch, average)
    combine_kernel<<<NR*DIq/256, 256>>>(yf, yb, yc);

    // 8. out_proj: (4096,1024) x (512,1024)^T -> (4096,512) into d_out
    {
        GP g{yc, W_out, out, nullptr};
        mma_gemm<128,64,64,32,0><<<dim3(DMq/64, NR/128, 1), 128>>>(
            g, g, NR, DMq, DIq, DIq, DIq, DMq);
    }
}